// round 2
// baseline (speedup 1.0000x reference)
#include <cuda_runtime.h>
#include <math.h>

#define B_ 8
#define S_ 1024
#define D_ 512
#define H_ 8
#define DK_ 64

#define TM 32
#define BJ 256
#define SS_STRIDE 1032     // 32 rows of scores, 16B-aligned rows
#define SQD_STRIDE 136     // Q duplicated along dk: [row][2*k]
#define SKT_STRIDE 264     // K transposed [k][j] (j swizzled in 8-blocks)
#define SV_STRIDE 68       // V row-major [j][d]

typedef unsigned long long ull;

__device__ __forceinline__ void fma2(ull &d, ull a, ull b){
    asm("fma.rn.f32x2 %0, %1, %2, %0;" : "+l"(d) : "l"(a), "l"(b));
}
__device__ __forceinline__ ull pack2(float lo, float hi){
    ull d; asm("mov.b64 %0, {%1, %2};" : "=l"(d) : "f"(lo), "f"(hi)); return d;
}
__device__ __forceinline__ float2 unpack2(ull v){
    float2 f; asm("mov.b64 {%0, %1}, %2;" : "=f"(f.x), "=f"(f.y) : "l"(v)); return f;
}

// scratch (device globals; no allocation allowed)
__device__ float g_qk[B_*H_*S_*DK_];   // 16 MB, q == k (kq_same)
__device__ float g_v [B_*H_*S_*DK_];   // 16 MB
__device__ float g_attn[B_*S_*D_];     // 16 MB

// ---------------------------------------------------------------------------
// Generic 128x128 fp32 GEMM with f32x2 FMA:  dst = A @ W^T + bias
// A: [M=8192, 512], W: [512, 512] row-major (we use W rows as "N").
// head_split=1 -> scatter output to [b,h,s,dk] layout.
// ---------------------------------------------------------------------------
__global__ __launch_bounds__(256) void gemm128(
    const float* __restrict__ A, const float* __restrict__ W,
    const float* __restrict__ bias, float* __restrict__ dst, int head_split)
{
    __shared__ float sAd[16*264];   // [kk][2*m] duplicated
    __shared__ float sB [16*132];   // [kk][n]

    const int m0 = blockIdx.y*128, n0 = blockIdx.x*128;
    const int tid = threadIdx.x;
    const int tx = tid & 15, ty = tid >> 4;
    const int lrow = tid >> 1;          // 0..127
    const int lk   = (tid & 1) * 8;     // 0 or 8

    ull acc[8][4];
    #pragma unroll
    for (int r=0;r<8;++r)
        #pragma unroll
        for (int p=0;p<4;++p) acc[r][p]=0ULL;

    for (int k0=0; k0<D_; k0+=16){
        float4 a0 = *(const float4*)(A + (long)(m0+lrow)*D_ + k0+lk);
        float4 a1 = *(const float4*)(A + (long)(m0+lrow)*D_ + k0+lk+4);
        float4 b0 = *(const float4*)(W + (long)(n0+lrow)*D_ + k0+lk);
        float4 b1 = *(const float4*)(W + (long)(n0+lrow)*D_ + k0+lk+4);
        __syncthreads();
        {
            float* pa = sAd + lk*264 + 2*lrow;
            pa[0*264+0]=a0.x; pa[0*264+1]=a0.x;
            pa[1*264+0]=a0.y; pa[1*264+1]=a0.y;
            pa[2*264+0]=a0.z; pa[2*264+1]=a0.z;
            pa[3*264+0]=a0.w; pa[3*264+1]=a0.w;
            pa[4*264+0]=a1.x; pa[4*264+1]=a1.x;
            pa[5*264+0]=a1.y; pa[5*264+1]=a1.y;
            pa[6*264+0]=a1.z; pa[6*264+1]=a1.z;
            pa[7*264+0]=a1.w; pa[7*264+1]=a1.w;
            float* pb = sB + lk*132 + lrow;
            pb[0*132]=b0.x; pb[1*132]=b0.y; pb[2*132]=b0.z; pb[3*132]=b0.w;
            pb[4*132]=b1.x; pb[5*132]=b1.y; pb[6*132]=b1.z; pb[7*132]=b1.w;
        }
        __syncthreads();
        #pragma unroll
        for (int kk=0; kk<16; ++kk){
            const float* ab = sAd + kk*264 + ty*16;
            ulonglong2 aA = *(const ulonglong2*)(ab);
            ulonglong2 aB = *(const ulonglong2*)(ab+4);
            ulonglong2 aC = *(const ulonglong2*)(ab+8);
            ulonglong2 aD = *(const ulonglong2*)(ab+12);
            const float* bb = sB + kk*132 + tx*8;
            ulonglong2 b01 = *(const ulonglong2*)(bb);
            ulonglong2 b23 = *(const ulonglong2*)(bb+4);
            #define FMAROW(r, ap) \
                fma2(acc[r][0], ap, b01.x); fma2(acc[r][1], ap, b01.y); \
                fma2(acc[r][2], ap, b23.x); fma2(acc[r][3], ap, b23.y);
            FMAROW(0, aA.x) FMAROW(1, aA.y)
            FMAROW(2, aB.x) FMAROW(3, aB.y)
            FMAROW(4, aC.x) FMAROW(5, aC.y)
            FMAROW(6, aD.x) FMAROW(7, aD.y)
            #undef FMAROW
        }
    }

    const int n = n0 + tx*8;
    float4 bi0 = *(const float4*)(bias + n);
    float4 bi1 = *(const float4*)(bias + n + 4);
    #pragma unroll
    for (int r=0; r<8; ++r){
        int m = m0 + ty*8 + r;
        float2 c0 = unpack2(acc[r][0]);
        float2 c1 = unpack2(acc[r][1]);
        float2 c2 = unpack2(acc[r][2]);
        float2 c3 = unpack2(acc[r][3]);
        float4 v0; v0.x=c0.x+bi0.x; v0.y=c0.y+bi0.y; v0.z=c1.x+bi0.z; v0.w=c1.y+bi0.w;
        float4 v1; v1.x=c2.x+bi1.x; v1.y=c2.y+bi1.y; v1.z=c3.x+bi1.z; v1.w=c3.y+bi1.w;
        float* p;
        if (head_split){
            int hh = n >> 6, dd = n & 63;
            int bb2 = m >> 10, ss = m & 1023;
            p = dst + (((long)bb2*H_ + hh)*S_ + ss)*DK_ + dd;
        } else {
            p = dst + (long)m*D_ + n;
        }
        *(float4*)p = v0;
        *(float4*)(p+4) = v1;
    }
}

// ---------------------------------------------------------------------------
// Attention with distance decay. One block = 32 query rows of one (b,h).
// Scores in SMEM (32 x up to 1024); softmax chain register-resident.
// ---------------------------------------------------------------------------
__global__ __launch_bounds__(256) void attn_kernel(
    const float* __restrict__ utT, const float* __restrict__ gammas)
{
    extern __shared__ float smem[];
    float* sS   = smem;                       // 32*1032
    float* sQd  = sS  + TM*SS_STRIDE;         // 32*136
    float* sKV  = sQd + TM*SQD_STRIDE;        // 17408 floats (K^T or V tile)
    float* sInv = sKV + 17408;                // 32

    const int i0 = blockIdx.x * TM;
    const int h  = blockIdx.y;
    const int b  = blockIdx.z;
    const int tid = threadIdx.x;
    const long bh = (long)(b*H_ + h);
    const float* Kbase = g_qk + bh*(long)(S_*DK_);
    const float* Vbase = g_v  + bh*(long)(S_*DK_);
    const int TJn  = (i0 + TM + BJ - 1) / BJ;
    const int JMAX = TJn * BJ;

    // ---- load Q tile duplicated: sQd[row][2k] = sQd[row][2k+1] = q ----
    #pragma unroll
    for (int it=0; it<2; ++it){
        int idx = tid + it*256;          // 0..511 = 32 rows * 16 float4
        int row = idx >> 4, c4 = (idx & 15)*4;
        float4 v = *(const float4*)(Kbase + (long)(i0+row)*DK_ + c4);
        float* p = sQd + row*SQD_STRIDE + c4*2;
        p[0]=v.x; p[1]=v.x; p[2]=v.y; p[3]=v.y;
        p[4]=v.z; p[5]=v.z; p[6]=v.w; p[7]=v.w;
    }

    const int tx = tid & 31;    // 8-col group for score GEMM
    const int ty = tid >> 5;    // warp -> 4 rows
    const float kscale = 0.125f;  // 1/sqrt(64)

    // ---- score GEMM: sS[i][j] = (q_i . k_j)/8 * utT[b,i,j] ----
    for (int jt=0; jt<TJn; ++jt){
        const int j0 = jt*BJ;
        __syncthreads();
        // K tile transposed with 8-block XOR swizzle on j
        #pragma unroll
        for (int it=0; it<16; ++it){
            int idx = tid + it*256;      // 0..4095
            int row = idx >> 4;          // 0..255 (j)
            int c4  = (idx & 15)*4;      // k base
            float4 v = *(const float4*)(Kbase + (long)(j0+row)*DK_ + c4);
            int rb = row >> 3, rl = row & 7;
            sKV[(c4+0)*SKT_STRIDE + ((rb ^ (((c4+0)>>2)&3))<<3) + rl] = v.x;
            sKV[(c4+1)*SKT_STRIDE + ((rb ^ (((c4+1)>>2)&3))<<3) + rl] = v.y;
            sKV[(c4+2)*SKT_STRIDE + ((rb ^ (((c4+2)>>2)&3))<<3) + rl] = v.z;
            sKV[(c4+3)*SKT_STRIDE + ((rb ^ (((c4+3)>>2)&3))<<3) + rl] = v.w;
        }
        __syncthreads();

        ull acc[4][4];
        #pragma unroll
        for (int r=0;r<4;++r)
            #pragma unroll
            for (int p=0;p<4;++p) acc[r][p]=0ULL;

        #pragma unroll 8
        for (int kk=0; kk<DK_; ++kk){
            const float* bbase = sKV + kk*SKT_STRIDE + ((tx ^ ((kk>>2)&3))<<3);
            ulonglong2 b01 = *(const ulonglong2*)(bbase);
            ulonglong2 b23 = *(const ulonglong2*)(bbase+4);
            ull a0 = *(const ull*)(sQd + (ty*4+0)*SQD_STRIDE + kk*2);
            ull a1 = *(const ull*)(sQd + (ty*4+1)*SQD_STRIDE + kk*2);
            ull a2 = *(const ull*)(sQd + (ty*4+2)*SQD_STRIDE + kk*2);
            ull a3 = *(const ull*)(sQd + (ty*4+3)*SQD_STRIDE + kk*2);
            #define SROW(r, ap) \
                fma2(acc[r][0], ap, b01.x); fma2(acc[r][1], ap, b01.y); \
                fma2(acc[r][2], ap, b23.x); fma2(acc[r][3], ap, b23.y);
            SROW(0, a0) SROW(1, a1) SROW(2, a2) SROW(3, a3)
            #undef SROW
        }

        const int jl = j0 + tx*8;
        #pragma unroll
        for (int r=0; r<4; ++r){
            int gi = i0 + ty*4 + r;
            const float* up = utT + ((long)b*S_ + gi)*S_ + jl;
            float4 u0 = *(const float4*)up;
            float4 u1 = *(const float4*)(up+4);
            float2 c0 = unpack2(acc[r][0]);
            float2 c1 = unpack2(acc[r][1]);
            float2 c2 = unpack2(acc[r][2]);
            float2 c3 = unpack2(acc[r][3]);
            float* prow = sS + (ty*4+r)*SS_STRIDE + jl;
            float4 w0; w0.x=c0.x*kscale*u0.x; w0.y=c0.y*kscale*u0.y;
                       w0.z=c1.x*kscale*u0.z; w0.w=c1.y*kscale*u0.w;
            float4 w1; w1.x=c2.x*kscale*u1.x; w1.y=c2.y*kscale*u1.y;
                       w1.z=c3.x*kscale*u1.z; w1.w=c3.y*kscale*u1.w;
            *(float4*)prow = w0;
            *(float4*)(prow+4) = w1;
        }
    }
    __syncthreads();

    // ---- register-resident: softmax1 -> cumsum -> decay -> exp2 ----
    {
        const int wid = tid >> 5, lane = tid & 31;
        const unsigned FULL = 0xffffffffu;
        const float gh = -log1pf(__expf(gammas[h]));   // -softplus(gamma)

        #pragma unroll 1
        for (int q=0; q<4; ++q){
            int r  = wid*4 + q;
            int gi = i0 + r;
            float* row = sS + r*SS_STRIDE;

            float sv[32];
            float cu[32];
            float mx = -1e30f;
            #pragma unroll
            for (int c=0; c<32; ++c){
                if (c*32 <= gi){                       // warp-uniform
                    int j = c*32 + lane;
                    float s = row[j];
                    sv[c] = s;
                    if (j <= gi) mx = fmaxf(mx, s);
                }
            }
            #pragma unroll
            for (int o=16; o>0; o>>=1) mx = fmaxf(mx, __shfl_xor_sync(FULL, mx, o));

            float carry = 0.f;
            #pragma unroll
            for (int c=0; c<32; ++c){
                if (c*32 <= gi){
                    int j = c*32 + lane;
                    float e = (j <= gi) ? __expf(sv[c] - mx) : 0.f;
                    float v = e;
                    #pragma unroll
                    for (int o=1; o<32; o<<=1){
                        float t = __shfl_up_sync(FULL, v, o);
                        if (lane >= o) v += t;
                    }
                    cu[c] = carry + v;
                    carry += __shfl_sync(FULL, v, 31);
                }
            }
            const float sm  = carry;
            const float inv = 1.f / sm;

            float mx2 = -1e30f;
            #pragma unroll
            for (int c=0; c<32; ++c){
                if (c*32 <= gi){
                    int j = c*32 + lane;
                    float rem = fmaxf(0.f, (sm - cu[c]) * inv);
                    float pe  = fabsf((float)(gi - j));
                    float y   = rem * pe;
                    float dist = (y > 0.f) ? y * __frsqrt_rn(y) : 0.f;
                    float te = fmaxf(__expf(dist * gh), 1e-5f);
                    float s2 = sv[c] * te;
                    sv[c] = s2;
                    if (j <= gi) mx2 = fmaxf(mx2, s2);
                }
            }
            #pragma unroll
            for (int o=16; o>0; o>>=1) mx2 = fmaxf(mx2, __shfl_xor_sync(FULL, mx2, o));

            float sm2 = 0.f;
            #pragma unroll
            for (int c=0; c<32; ++c){
                int j = c*32 + lane;
                if (c*32 <= gi){
                    float e2 = (j <= gi) ? __expf(sv[c] - mx2) : 0.f;
                    sm2 += e2;
                    row[j] = e2;
                } else if (j < JMAX){
                    row[j] = 0.f;
                }
            }
            #pragma unroll
            for (int o=16; o>0; o>>=1) sm2 += __shfl_xor_sync(FULL, sm2, o);
            if (lane == 0) sInv[r] = 1.f / sm2;
        }
    }
    __syncthreads();

    // ---- output GEMM: out[i][d] = inv2_i * sum_j e2[i][j] * v[j][d] ----
    {
        const int rg = tid >> 3;        // 0..31 output row (8 threads share it)
        const int dg = tid & 7;         // d = dg*8 .. +7
        ull acc2[4] = {0ULL,0ULL,0ULL,0ULL};

        for (int jt=0; jt<TJn; ++jt){
            const int j0 = jt*BJ;
            __syncthreads();
            #pragma unroll
            for (int it=0; it<16; ++it){
                int idx = tid + it*256;
                int row = idx >> 4, c4 = (idx & 15)*4;
                float4 v = *(const float4*)(Vbase + (long)(j0+row)*DK_ + c4);
                *(float4*)(sKV + row*SV_STRIDE + c4) = v;
            }
            __syncthreads();
            const float* prow = sS + rg*SS_STRIDE + j0;
            #pragma unroll 4
            for (int jj=0; jj<BJ; jj+=4){
                float4 p4 = *(const float4*)(prow + jj);
                #define OSTEP(u, pv) { \
                    ull pp = pack2(pv, pv); \
                    const float* vb = sKV + (jj+u)*SV_STRIDE + dg*8; \
                    ulonglong2 va = *(const ulonglong2*)(vb); \
                    ulonglong2 vc = *(const ulonglong2*)(vb+4); \
                    fma2(acc2[0], pp, va.x); fma2(acc2[1], pp, va.y); \
                    fma2(acc2[2], pp, vc.x); fma2(acc2[3], pp, vc.y); }
                OSTEP(0, p4.x) OSTEP(1, p4.y) OSTEP(2, p4.z) OSTEP(3, p4.w)
                #undef OSTEP
            }
        }

        float sc = sInv[rg];
        float2 o0 = unpack2(acc2[0]);
        float2 o1 = unpack2(acc2[1]);
        float2 o2 = unpack2(acc2[2]);
        float2 o3 = unpack2(acc2[3]);
        float4 w0; w0.x=o0.x*sc; w0.y=o0.y*sc; w0.z=o1.x*sc; w0.w=o1.y*sc;
        float4 w1; w1.x=o2.x*sc; w1.y=o2.y*sc; w1.z=o3.x*sc; w1.w=o3.y*sc;
        float* op = g_attn + ((long)b*S_ + i0 + rg)*D_ + h*DK_ + dg*8;
        *(float4*)op = w0;
        *(float4*)(op+4) = w1;
    }
}

// ---------------------------------------------------------------------------
extern "C" void kernel_launch(void* const* d_in, const int* in_sizes, int n_in,
                              void* d_out, int out_size)
{
    const float* x      = (const float*)d_in[0];
    const float* utT    = (const float*)d_in[1];
    const float* Wk     = (const float*)d_in[2];
    const float* bk     = (const float*)d_in[3];
    const float* Wv     = (const float*)d_in[4];
    const float* bv     = (const float*)d_in[5];
    const float* Wo     = (const float*)d_in[6];
    const float* bo     = (const float*)d_in[7];
    const float* gammas = (const float*)d_in[8];
    float* out = (float*)d_out;

    float* qk; cudaGetSymbolAddress((void**)&qk, g_qk);
    float* vv; cudaGetSymbolAddress((void**)&vv, g_v);
    float* at; cudaGetSymbolAddress((void**)&at, g_attn);

    dim3 ggrid(D_/128, (B_*S_)/128);

    // QK + V projections (head-split output)
    gemm128<<<ggrid, 256>>>(x, Wk, bk, qk, 1);
    gemm128<<<ggrid, 256>>>(x, Wv, bv, vv, 1);

    // attention
    size_t smem_bytes = (size_t)(TM*SS_STRIDE + TM*SQD_STRIDE + 17408 + 32) * sizeof(float);
    cudaFuncSetAttribute(attn_kernel, cudaFuncAttributeMaxDynamicSharedMemorySize, (int)smem_bytes);
    attn_kernel<<<dim3(S_/TM, H_, B_), 256, smem_bytes>>>(utT, gammas);

    // output projection (plain layout)
    gemm128<<<ggrid, 256>>>(at, Wo, bo, out, 0);
}